// round 17
// baseline (speedup 1.0000x reference)
#include <cuda_runtime.h>
#include <cuda_fp16.h>
#include <math_constants.h>
#include <mma.h>
using namespace nvcuda;

#define N_NODES 50000
#define N_EDGES 1600000
#define ET      (N_EDGES + N_NODES)
#define EQ      (N_EDGES / 4)
#define HID     128
#define NG      512
#define DEG_CAP 64
#define SCAN_B  1024
#define NB      ((N_NODES + SCAN_B - 1) / SCAN_B)   // 49
#define NPAD    50048                                // 391*128

// ---------------- scratch (device globals; allocation-free) ----------------
__device__ __half g_hh[(size_t)N_NODES * HID];
__device__ float g_agg[(size_t)N_NODES * HID];
__device__ float g_tmp[(size_t)NPAD * HID];          // fp32 C of layer-2 GEMM
__device__ __half g_w2hi[HID * HID];                 // W2 hi fp16, col-major [n][k]
__device__ __half g_w2lo[HID * HID];                 // W2 lo fp16 (residual)
__device__ float g_was2[HID];                        // W2 @ a_src2 (exact fp32)
__device__ float g_wad2[HID];                        // W2 @ a_dst2
__device__ float g_asrc[N_NODES];
__device__ float g_adst[N_NODES];
__device__ int   g_rowptr[N_NODES + 1];
__device__ int   g_cursor[N_NODES];
__device__ int   g_csrc[ET];
__device__ int   g_btot[NB];
__device__ float g_maxp[NG * HID];
__device__ float g_sump[NG * HID];
__device__ int   g_cnt[NG];
__device__ int   g_lmax[2] = {(int)0x807FFFFF, (int)0x807FFFFF};

__device__ __forceinline__ int fkey(float f) {
    int b = __float_as_int(f);
    return b >= 0 ? b : b ^ 0x7FFFFFFF;
}
__device__ __forceinline__ float funkey(int k) {
    return __int_as_float(k >= 0 ? k : k ^ 0x7FFFFFFF);
}

// ---------------- f32x2 packed helpers ----------------
__device__ __forceinline__ unsigned long long fma2(unsigned long long a,
                                                   unsigned long long b,
                                                   unsigned long long c) {
    unsigned long long d;
    asm("fma.rn.f32x2 %0, %1, %2, %3;" : "=l"(d) : "l"(a), "l"(b), "l"(c));
    return d;
}
__device__ __forceinline__ unsigned long long pack2(float lo, float hi) {
    unsigned long long r;
    asm("mov.b64 %0, {%1, %2};" : "=l"(r) : "f"(lo), "f"(hi));
    return r;
}
__device__ __forceinline__ void unpack2(unsigned long long v, float& lo, float& hi) {
    asm("mov.b64 {%0, %1}, %2;" : "=f"(lo), "=f"(hi) : "l"(v));
}

// ---------------- init ----------------
__global__ void init_kernel() {
    int i = blockIdx.x * blockDim.x + threadIdx.x;
    if (i < N_NODES) g_cursor[i] = 1;
    if (i < NG * HID) { g_maxp[i] = 0.f; g_sump[i] = 0.f; }
    if (i < NG) g_cnt[i] = 0;
}

// ---------------- W2 -> fp16 hi/lo col-major ----------------
__global__ void w2split_kernel(const float* __restrict__ W2) {
    int i = blockIdx.x * blockDim.x + threadIdx.x;
    if (i < HID * HID) {
        int k = i >> 7, n = i & 127;
        float w = W2[k * HID + n];
        __half hi = __float2half_rn(w);
        __half lo = __float2half_rn(w - __half2float(hi));
        g_w2hi[n * HID + k] = hi;
        g_w2lo[n * HID + k] = lo;
    }
}

// ---------------- w_as2/w_ad2 = W2 @ a2 (exact fp32) ----------------
// 128 warps, warp k computes dot(W2[k,:], a)
__global__ void wvec_kernel(const float* __restrict__ W2,
                            const float* __restrict__ as2,
                            const float* __restrict__ ad2) {
    int k = (blockIdx.x * blockDim.x + threadIdx.x) >> 5;
    int lane = threadIdx.x & 31;
    if (k >= HID) return;
    float4 wv = *(const float4*)(W2 + k * HID + lane * 4);
    float4 a1 = *(const float4*)(as2 + lane * 4);
    float4 a2 = *(const float4*)(ad2 + lane * 4);
    float s1 = wv.x * a1.x + wv.y * a1.y + wv.z * a1.z + wv.w * a1.w;
    float s2 = wv.x * a2.x + wv.y * a2.y + wv.z * a2.z + wv.w * a2.w;
#pragma unroll
    for (int o = 16; o; o >>= 1) {
        s1 += __shfl_xor_sync(0xffffffffu, s1, o);
        s2 += __shfl_xor_sync(0xffffffffu, s2, o);
    }
    if (lane == 0) { g_was2[k] = s1; g_wad2[k] = s2; }
}

// ---------------- histogram ----------------
__global__ void hist_kernel(const int* __restrict__ ei) {
    int t = blockIdx.x * blockDim.x + threadIdx.x;
    if (t >= EQ) return;
    int4 d = *(const int4*)(ei + N_EDGES + t * 4);
    atomicAdd(&g_cursor[d.x], 1);
    atomicAdd(&g_cursor[d.y], 1);
    atomicAdd(&g_cursor[d.z], 1);
    atomicAdd(&g_cursor[d.w], 1);
}

// ---------------- hierarchical scan ----------------
__global__ __launch_bounds__(SCAN_B) void scan1_kernel() {
    __shared__ int sh[32];
    int b = blockIdx.x, t = threadIdx.x, lane = t & 31, wid = t >> 5;
    int idx = b * SCAN_B + t;
    int v = (idx < N_NODES) ? g_cursor[idx] : 0;
    int x = v;
#pragma unroll
    for (int o = 1; o < 32; o <<= 1) {
        int y = __shfl_up_sync(0xffffffffu, x, o);
        if (lane >= o) x += y;
    }
    if (lane == 31) sh[wid] = x;
    __syncthreads();
    if (wid == 0) {
        int y = sh[lane];
#pragma unroll
        for (int o = 1; o < 32; o <<= 1) {
            int z = __shfl_up_sync(0xffffffffu, y, o);
            if (lane >= o) y += z;
        }
        sh[lane] = y;
    }
    __syncthreads();
    int offs = wid ? sh[wid - 1] : 0;
    if (idx < N_NODES) g_rowptr[idx] = offs + x - v;
    if (t == SCAN_B - 1) g_btot[b] = offs + x;
}

__global__ void scan2_kernel() {
    __shared__ int wsum[2];
    int t = threadIdx.x, lane = t & 31, wid = t >> 5;
    int v = (t < NB) ? g_btot[t] : 0;
    int x = v;
#pragma unroll
    for (int o = 1; o < 32; o <<= 1) {
        int y = __shfl_up_sync(0xffffffffu, x, o);
        if (lane >= o) x += y;
    }
    if (lane == 31) wsum[wid] = x;
    __syncthreads();
    if (wid == 1) x += wsum[0];
    if (t < NB) g_btot[t] = x - v;
    if (t == NB - 1) g_rowptr[N_NODES] = x;
}

__global__ void scan3_kernel() {
    int i = blockIdx.x * blockDim.x + threadIdx.x;
    if (i < N_NODES) {
        int ex = g_rowptr[i] + g_btot[i / SCAN_B];
        g_rowptr[i] = ex;
        g_cursor[i] = ex;
    }
}

// ---------------- scatter ----------------
__global__ void scatter_kernel(const int* __restrict__ ei) {
    int t = blockIdx.x * blockDim.x + threadIdx.x;
    if (t < EQ) {
        int4 s = *(const int4*)(ei + t * 4);
        int4 d = *(const int4*)(ei + N_EDGES + t * 4);
        int p0 = atomicAdd(&g_cursor[d.x], 1);
        int p1 = atomicAdd(&g_cursor[d.y], 1);
        int p2 = atomicAdd(&g_cursor[d.z], 1);
        int p3 = atomicAdd(&g_cursor[d.w], 1);
        g_csrc[p0] = s.x; g_csrc[p1] = s.y; g_csrc[p2] = s.z; g_csrc[p3] = s.w;
    } else {
        int v = t - EQ;
        if (v < N_NODES) {
            int p = atomicAdd(&g_cursor[v], 1);
            g_csrc[p] = v;
        }
    }
}

// -------- layer-1 GEMM (FFMA, fp32-exact inputs): unchanged ---------------
__global__ __launch_bounds__(256, 2) void gemm_fused(const float* __restrict__ A_ext,
                                                     const float* __restrict__ W,
                                                     const float* __restrict__ av,
                                                     const float* __restrict__ adv,
                                                     int lx) {
    const float* __restrict__ A = A_ext ? A_ext : g_agg;
    __shared__ float As[128 * 36];
    __shared__ float Ws[32 * 132];
    __shared__ int smax;
    const int tid = threadIdx.x;
    const int row0 = blockIdx.x * 128;
    const int tx = tid & 15, ty = tid >> 4;

    unsigned long long acc2[8][4];
#pragma unroll
    for (int i = 0; i < 8; i++)
#pragma unroll
        for (int j = 0; j < 4; j++) acc2[i][j] = 0ull;

    for (int k0 = 0; k0 < 128; k0 += 32) {
#pragma unroll
        for (int i = 0; i < 4; i++) {
            int f = tid + i * 256;
            int r = f >> 3, kq = f & 7;
            int gr = row0 + r;
            float4 v = make_float4(0.f, 0.f, 0.f, 0.f);
            if (gr < N_NODES) v = *(const float4*)(A + (size_t)gr * HID + k0 + kq * 4);
            v.x = fmaxf(v.x, 0.f); v.y = fmaxf(v.y, 0.f);
            v.z = fmaxf(v.z, 0.f); v.w = fmaxf(v.w, 0.f);
            *(float4*)(&As[r * 36 + kq * 4]) = v;
        }
#pragma unroll
        for (int i = 0; i < 4; i++) {
            int f = tid + i * 256;
            int kk = f >> 5, cq = f & 31;
            float4 v = *(const float4*)(W + (size_t)(k0 + kk) * HID + cq * 4);
            *(float4*)(&Ws[kk * 132 + cq * 4]) = v;
        }
        __syncthreads();
#pragma unroll
        for (int k = 0; k < 32; k++) {
            float4 b0 = *(const float4*)(&Ws[k * 132 + tx * 4]);
            float4 b1 = *(const float4*)(&Ws[k * 132 + 64 + tx * 4]);
            unsigned long long bb[4];
            bb[0] = pack2(b0.x, b0.y); bb[1] = pack2(b0.z, b0.w);
            bb[2] = pack2(b1.x, b1.y); bb[3] = pack2(b1.z, b1.w);
#pragma unroll
            for (int i = 0; i < 8; i++) {
                float a = (i < 4) ? As[(ty * 4 + i) * 36 + k]
                                  : As[(64 + ty * 4 + (i - 4)) * 36 + k];
                unsigned long long aa = pack2(a, a);
#pragma unroll
                for (int j = 0; j < 4; j++) acc2[i][j] = fma2(aa, bb[j], acc2[i][j]);
            }
        }
        __syncthreads();
    }

    if (tid == 0) smax = (int)0x80000000;
    __syncthreads();

    float4 a1lo = *(const float4*)(av + tx * 4);
    float4 a1hi = *(const float4*)(av + 64 + tx * 4);
    float4 a2lo = *(const float4*)(adv + tx * 4);
    float4 a2hi = *(const float4*)(adv + 64 + tx * 4);
    const unsigned fullm = 0xffffffffu;
#pragma unroll
    for (int i = 0; i < 8; i++) {
        int gr = row0 + ((i < 4) ? (ty * 4 + i) : (64 + ty * 4 + (i - 4)));
        float c0, c1, c2, c3, c4, c5, c6, c7;
        unpack2(acc2[i][0], c0, c1); unpack2(acc2[i][1], c2, c3);
        unpack2(acc2[i][2], c4, c5); unpack2(acc2[i][3], c6, c7);
        float s1 = c0 * a1lo.x + c1 * a1lo.y + c2 * a1lo.z + c3 * a1lo.w
                 + c4 * a1hi.x + c5 * a1hi.y + c6 * a1hi.z + c7 * a1hi.w;
        float s2 = c0 * a2lo.x + c1 * a2lo.y + c2 * a2lo.z + c3 * a2lo.w
                 + c4 * a2hi.x + c5 * a2hi.y + c6 * a2hi.z + c7 * a2hi.w;
#pragma unroll
        for (int o = 8; o; o >>= 1) {
            s1 += __shfl_xor_sync(fullm, s1, o);
            s2 += __shfl_xor_sync(fullm, s2, o);
        }
        if (gr < N_NODES) {
            if (tx == 0) {
                g_asrc[gr] = s1;
                g_adst[gr] = s2;
                atomicMax(&smax, fkey(s1));
            }
            __half2 h0 = __floats2half2_rn(c0, c1);
            __half2 h1 = __floats2half2_rn(c2, c3);
            __half2 h2 = __floats2half2_rn(c4, c5);
            __half2 h3 = __floats2half2_rn(c6, c7);
            uint2 u0 = make_uint2(*(unsigned*)&h0, *(unsigned*)&h1);
            uint2 u1 = make_uint2(*(unsigned*)&h2, *(unsigned*)&h3);
            *(uint2*)(g_hh + (size_t)gr * HID + tx * 4)      = u0;
            *(uint2*)(g_hh + (size_t)gr * HID + 64 + tx * 4) = u1;
        }
    }
    __syncthreads();
    if (tid == 0) atomicMax(&g_lmax[lx], smax);
}

// -------- layer-2 GEMM: wmma, A split hi/lo (2 MMA chains) -> g_tmp --------
// C = (A_hi + A_lo) @ W_hi + A_hi @ W_lo   (A-quant removed; W-lo term
// recovers most of W-quant). Messages only; logits come from exact path.
__global__ __launch_bounds__(256) void gemm2_wmma() {
    __shared__ __half Ahi[128 * 72];   // 64-col chunk, stride 72 (144B rows)
    __shared__ __half Alo[128 * 72];
    const int tid = threadIdx.x;
    const int warp = tid >> 5;          // 0..7, rows [warp*16, +16)
    const int row0 = blockIdx.x * 128;
    const int rowW = warp * 16;

    wmma::fragment<wmma::accumulator, 16, 16, 16, float> acc[8];
#pragma unroll
    for (int nt = 0; nt < 8; nt++) wmma::fill_fragment(acc[nt], 0.f);

    for (int kc = 0; kc < 128; kc += 64) {
        // stage A chunk (relu + hi/lo split)
        {
            int r = tid >> 1, seg = tid & 1;
            int gr = row0 + r;
            __half* dhi = Ahi + r * 72 + seg * 32;
            __half* dlo = Alo + r * 72 + seg * 32;
            if (gr < N_NODES) {
                const float* src = g_agg + (size_t)gr * HID + kc + seg * 32;
#pragma unroll
                for (int j = 0; j < 8; j++) {
                    float4 v = *(const float4*)(src + j * 4);
                    v.x = fmaxf(v.x, 0.f); v.y = fmaxf(v.y, 0.f);
                    v.z = fmaxf(v.z, 0.f); v.w = fmaxf(v.w, 0.f);
                    __half hx = __float2half_rn(v.x), hy = __float2half_rn(v.y);
                    __half hz = __float2half_rn(v.z), hw = __float2half_rn(v.w);
                    __half lx2 = __float2half_rn(v.x - __half2float(hx));
                    __half ly2 = __float2half_rn(v.y - __half2float(hy));
                    __half lz2 = __float2half_rn(v.z - __half2float(hz));
                    __half lw2 = __float2half_rn(v.w - __half2float(hw));
                    __half2 p0 = __halves2half2(hx, hy), p1 = __halves2half2(hz, hw);
                    __half2 q0 = __halves2half2(lx2, ly2), q1 = __halves2half2(lz2, lw2);
                    *(uint2*)(dhi + j * 4) = make_uint2(*(unsigned*)&p0, *(unsigned*)&p1);
                    *(uint2*)(dlo + j * 4) = make_uint2(*(unsigned*)&q0, *(unsigned*)&q1);
                }
            } else {
#pragma unroll
                for (int j = 0; j < 8; j++) {
                    *(uint2*)(dhi + j * 4) = make_uint2(0u, 0u);
                    *(uint2*)(dlo + j * 4) = make_uint2(0u, 0u);
                }
            }
        }
        __syncthreads();

        for (int k = 0; k < 64; k += 16) {
            wmma::fragment<wmma::matrix_a, 16, 16, 16, __half, wmma::row_major> afh, afl;
            wmma::load_matrix_sync(afh, Ahi + rowW * 72 + k, 72);
            wmma::load_matrix_sync(afl, Alo + rowW * 72 + k, 72);
#pragma unroll
            for (int nt = 0; nt < 8; nt++) {
                wmma::fragment<wmma::matrix_b, 16, 16, 16, __half, wmma::col_major> bfh, bfl;
                wmma::load_matrix_sync(bfh, g_w2hi + nt * 16 * HID + kc + k, HID);
                wmma::load_matrix_sync(bfl, g_w2lo + nt * 16 * HID + kc + k, HID);
                wmma::mma_sync(acc[nt], afh, bfh, acc[nt]);
                wmma::mma_sync(acc[nt], afl, bfh, acc[nt]);
                wmma::mma_sync(acc[nt], afh, bfl, acc[nt]);
            }
        }
        __syncthreads();
    }
#pragma unroll
    for (int nt = 0; nt < 8; nt++)
        wmma::store_matrix_sync(g_tmp + (size_t)(row0 + rowW) * HID + nt * 16,
                                acc[nt], HID, wmma::mem_row_major);
}

// -------- post2: EXACT logits from g_agg (associativity) + fp16 hh ---------
__global__ void post2_kernel() {
    __shared__ int smax;
    if (threadIdx.x == 0) smax = (int)0x80000000;
    __syncthreads();
    int w = (blockIdx.x * blockDim.x + threadIdx.x) >> 5;
    int lane = threadIdx.x & 31;
    if (w < N_NODES) {
        // exact logits: dot(relu(agg), W2 @ a)
        float4 g = *(const float4*)(g_agg + (size_t)w * HID + lane * 4);
        g.x = fmaxf(g.x, 0.f); g.y = fmaxf(g.y, 0.f);
        g.z = fmaxf(g.z, 0.f); g.w = fmaxf(g.w, 0.f);
        float4 a1 = *(const float4*)(g_was2 + lane * 4);
        float4 a2 = *(const float4*)(g_wad2 + lane * 4);
        float s1 = g.x * a1.x + g.y * a1.y + g.z * a1.z + g.w * a1.w;
        float s2 = g.x * a2.x + g.y * a2.y + g.z * a2.z + g.w * a2.w;
#pragma unroll
        for (int o = 16; o; o >>= 1) {
            s1 += __shfl_xor_sync(0xffffffffu, s1, o);
            s2 += __shfl_xor_sync(0xffffffffu, s2, o);
        }
        // h: convert wmma C to fp16
        float4 cv = *(const float4*)(g_tmp + (size_t)w * HID + lane * 4);
        __half2 h0 = __floats2half2_rn(cv.x, cv.y);
        __half2 h1 = __floats2half2_rn(cv.z, cv.w);
        *(uint2*)(g_hh + (size_t)w * HID + lane * 4) =
            make_uint2(*(unsigned*)&h0, *(unsigned*)&h1);
        if (lane == 0) {
            g_asrc[w] = s1;
            g_adst[w] = s2;
            atomicMax(&smax, fkey(s1));
        }
    }
    __syncthreads();
    if (threadIdx.x == 0) atomicMax(&g_lmax[1], smax);
}

// ------ GAT aggregation: warp/node, single weight pass (global-max bound) --
__global__ __launch_bounds__(256) void gat_agg_kernel(const float* __restrict__ bias,
                                                      const int* __restrict__ batch,
                                                      int pool_mode, int lx) {
    __shared__ float shw[8][DEG_CAP];
    int w = (blockIdx.x * blockDim.x + threadIdx.x) >> 5;
    int lane = threadIdx.x & 31;
    int wid = (threadIdx.x >> 5) & 7;
    if (w >= N_NODES) return;
    int beg = g_rowptr[w];
    int n = g_rowptr[w + 1] - beg;
    float ad = g_adst[w];
    float mm = funkey(g_lmax[lx]) + ad;
    float m = mm > 0.f ? mm : 0.2f * mm;
    bool small = (n <= DEG_CAP);

    float ssum = 0.f;
    for (int i = lane; i < n; i += 32) {
        int s = g_csrc[beg + i];
        float l = g_asrc[s] + ad;
        l = l > 0.f ? l : 0.2f * l;
        float e = __expf(l - m);
        ssum += e;
        if (small) shw[wid][i] = e;
    }
#pragma unroll
    for (int o = 16; o; o >>= 1) ssum += __shfl_xor_sync(0xffffffffu, ssum, o);
    float inv = 1.f / ssum;
    __syncwarp();

    float4 acc = make_float4(0.f, 0.f, 0.f, 0.f);
    const int col = lane << 2;
    if (small) {
        int i = 0;
        for (; i + 4 <= n; i += 4) {
            int s0 = g_csrc[beg + i + 0];
            int s1 = g_csrc[beg + i + 1];
            int s2 = g_csrc[beg + i + 2];
            int s3 = g_csrc[beg + i + 3];
            float e0 = shw[wid][i + 0], e1 = shw[wid][i + 1];
            float e2 = shw[wid][i + 2], e3 = shw[wid][i + 3];
            uint2 u0 = *(const uint2*)(g_hh + (size_t)s0 * HID + col);
            uint2 u1 = *(const uint2*)(g_hh + (size_t)s1 * HID + col);
            uint2 u2 = *(const uint2*)(g_hh + (size_t)s2 * HID + col);
            uint2 u3 = *(const uint2*)(g_hh + (size_t)s3 * HID + col);
            float2 f0a = __half22float2(*(__half2*)&u0.x), f0b = __half22float2(*(__half2*)&u0.y);
            float2 f1a = __half22float2(*(__half2*)&u1.x), f1b = __half22float2(*(__half2*)&u1.y);
            float2 f2a = __half22float2(*(__half2*)&u2.x), f2b = __half22float2(*(__half2*)&u2.y);
            float2 f3a = __half22float2(*(__half2*)&u3.x), f3b = __half22float2(*(__half2*)&u3.y);
            acc.x = fmaf(e0, f0a.x, acc.x); acc.y = fmaf(e0, f0a.y, acc.y);
            acc.z = fmaf(e0, f0b.x, acc.z); acc.w = fmaf(e0, f0b.y, acc.w);
            acc.x = fmaf(e1, f1a.x, acc.x); acc.y = fmaf(e1, f1a.y, acc.y);
            acc.z = fmaf(e1, f1b.x, acc.z); acc.w = fmaf(e1, f1b.y, acc.w);
            acc.x = fmaf(e2, f2a.x, acc.x); acc.y = fmaf(e2, f2a.y, acc.y);
            acc.z = fmaf(e2, f2b.x, acc.z); acc.w = fmaf(e2, f2b.y, acc.w);
            acc.x = fmaf(e3, f3a.x, acc.x); acc.y = fmaf(e3, f3a.y, acc.y);
            acc.z = fmaf(e3, f3b.x, acc.z); acc.w = fmaf(e3, f3b.y, acc.w);
        }
        for (; i < n; i++) {
            int s = g_csrc[beg + i];
            float e = shw[wid][i];
            uint2 u = *(const uint2*)(g_hh + (size_t)s * HID + col);
            float2 fa = __half22float2(*(__half2*)&u.x);
            float2 fb = __half22float2(*(__half2*)&u.y);
            acc.x = fmaf(e, fa.x, acc.x); acc.y = fmaf(e, fa.y, acc.y);
            acc.z = fmaf(e, fb.x, acc.z); acc.w = fmaf(e, fb.y, acc.w);
        }
    } else {
        for (int i = 0; i < n; i++) {
            int s = g_csrc[beg + i];
            float l = g_asrc[s] + ad;
            l = l > 0.f ? l : 0.2f * l;
            float e = __expf(l - m);
            uint2 u = *(const uint2*)(g_hh + (size_t)s * HID + col);
            float2 fa = __half22float2(*(__half2*)&u.x);
            float2 fb = __half22float2(*(__half2*)&u.y);
            acc.x = fmaf(e, fa.x, acc.x); acc.y = fmaf(e, fa.y, acc.y);
            acc.z = fmaf(e, fb.x, acc.z); acc.w = fmaf(e, fb.y, acc.w);
        }
    }
    float4 bv = *(const float4*)(bias + col);
    acc.x = fmaf(acc.x, inv, bv.x);
    acc.y = fmaf(acc.y, inv, bv.y);
    acc.z = fmaf(acc.z, inv, bv.z);
    acc.w = fmaf(acc.w, inv, bv.w);

    if (!pool_mode) {
        *(float4*)(&g_agg[(size_t)w * HID + col]) = acc;
    } else {
        acc.x = fmaxf(acc.x, 0.f); acc.y = fmaxf(acc.y, 0.f);
        acc.z = fmaxf(acc.z, 0.f); acc.w = fmaxf(acc.w, 0.f);
        int g = batch[w];
        int base = g * HID + col;
        atomicMax((int*)&g_maxp[base + 0], __float_as_int(acc.x));
        atomicMax((int*)&g_maxp[base + 1], __float_as_int(acc.y));
        atomicMax((int*)&g_maxp[base + 2], __float_as_int(acc.z));
        atomicMax((int*)&g_maxp[base + 3], __float_as_int(acc.w));
        atomicAdd(&g_sump[base + 0], acc.x);
        atomicAdd(&g_sump[base + 1], acc.y);
        atomicAdd(&g_sump[base + 2], acc.z);
        atomicAdd(&g_sump[base + 3], acc.w);
        if (lane == 0) atomicAdd(&g_cnt[g], 1);
    }
}

__global__ void final_kernel(const float* __restrict__ fcw, const float* __restrict__ fcb,
                             float* __restrict__ out) {
    int w = (blockIdx.x * blockDim.x + threadIdx.x) >> 5;
    int lane = threadIdx.x & 31;
    if (w >= NG) return;
    float4 mx = *(const float4*)(&g_maxp[w * HID + (lane << 2)]);
    float4 sm = *(const float4*)(&g_sump[w * HID + (lane << 2)]);
    float4 w1 = *(const float4*)(fcw + (lane << 2));
    float4 w2 = *(const float4*)(fcw + HID + (lane << 2));
    float c = fmaxf((float)g_cnt[w], 1.f);
    float p = mx.x * w1.x + mx.y * w1.y + mx.z * w1.z + mx.w * w1.w
            + (sm.x * w2.x + sm.y * w2.y + sm.z * w2.z + sm.w * w2.w) / c;
#pragma unroll
    for (int o = 16; o; o >>= 1) p += __shfl_xor_sync(0xffffffffu, p, o);
    if (lane == 0) out[w] = p + fcb[0];
}

// ---------------- launch ----------------
extern "C" void kernel_launch(void* const* d_in, const int* in_sizes, int n_in,
                              void* d_out, int out_size) {
    const float* x   = (const float*)d_in[0];
    const int*   ei  = (const int*)d_in[1];
    const int*   bat = (const int*)d_in[2];
    const float* W1  = (const float*)d_in[3];
    const float* as1 = (const float*)d_in[4];
    const float* ad1 = (const float*)d_in[5];
    const float* b1  = (const float*)d_in[6];
    const float* W2  = (const float*)d_in[7];
    const float* as2 = (const float*)d_in[8];
    const float* ad2 = (const float*)d_in[9];
    const float* b2  = (const float*)d_in[10];
    const float* fcw = (const float*)d_in[11];
    const float* fcb = (const float*)d_in[12];
    float* out = (float*)d_out;

    const int TB = 256;
    const int initBlocks = (NG * HID + TB - 1) / TB;
    const int histBlocks = (EQ + TB - 1) / TB;
    const int scatBlocks = (EQ + N_NODES + TB - 1) / TB;
    const int nodeBlocks = (N_NODES + TB - 1) / TB;
    const int warpNodeBlocks = (N_NODES * 32 + TB - 1) / TB;
    const int gemmBlocks = (N_NODES + 127) / 128;

    cudaStream_t s2;
    cudaEvent_t ev0, ev1;
    cudaStreamCreateWithFlags(&s2, cudaStreamNonBlocking);
    cudaEventCreateWithFlags(&ev0, cudaEventDisableTiming);
    cudaEventCreateWithFlags(&ev1, cudaEventDisableTiming);

    cudaEventRecord(ev0, 0);
    cudaStreamWaitEvent(s2, ev0, 0);

    // main: GEMM1 (FFMA, exact logits) — concurrent with CSR chain
    gemm_fused<<<gemmBlocks, TB>>>(x, W1, as1, ad1, 0);

    // s2: W2 split + exact logit vectors + CSR build chain
    w2split_kernel<<<(HID * HID + TB - 1) / TB, TB, 0, s2>>>(W2);
    wvec_kernel<<<(HID * 32 + TB - 1) / TB, TB, 0, s2>>>(W2, as2, ad2);
    init_kernel<<<initBlocks, TB, 0, s2>>>();
    hist_kernel<<<histBlocks, TB, 0, s2>>>(ei);
    scan1_kernel<<<NB, SCAN_B, 0, s2>>>();
    scan2_kernel<<<1, 64, 0, s2>>>();
    scan3_kernel<<<nodeBlocks, TB, 0, s2>>>();
    scatter_kernel<<<scatBlocks, TB, 0, s2>>>(ei);
    cudaEventRecord(ev1, s2);

    cudaStreamWaitEvent(0, ev1, 0);                   // join

    gat_agg_kernel<<<warpNodeBlocks, TB>>>(b1, bat, 0, 0);
    gemm2_wmma<<<gemmBlocks, TB>>>();
    post2_kernel<<<warpNodeBlocks, TB>>>();
    gat_agg_kernel<<<warpNodeBlocks, TB>>>(b2, bat, 1, 1);
    final_kernel<<<(NG * 32 + TB - 1) / TB, TB>>>(fcw, fcb, out);
}